// round 11
// baseline (speedup 1.0000x reference)
#include <cuda_runtime.h>
#include <cstdint>

#define HID   2048
#define MROWS 4096   // B*S
#define NHEAD 16
#define HDIM  128
#define SEQ   2048
#define BH    32     // B*NHEAD

// Scratch (no allocations allowed)
__device__ float g_Q [BH * SEQ * HDIM];       // [bh][s][d]   (tf32-rounded)
__device__ float g_K [BH * SEQ * HDIM];       // [bh][s][d]   (tf32-rounded)
__device__ float g_Vt[BH * HDIM * SEQ];       // [bh][d][s]   (tf32-rounded)
__device__ float g_attn[(size_t)MROWS * HID]; // [B*S][nh*hd] (tf32-rounded)
__device__ float g_xr[(size_t)MROWS * HID];   // rounded x
__device__ float g_Wr[4ull * HID * HID];      // rounded Wq,Wk,Wv,Wo (contiguous)
__device__ float g_bqkv[3 * HID];             // concat bq|bk|bv

// ---------------------------------------------------------------------------
// helpers
// ---------------------------------------------------------------------------
__device__ __forceinline__ void cp_async16(void* smem_dst, const void* gmem_src) {
    uint32_t s = (uint32_t)__cvta_generic_to_shared(smem_dst);
    asm volatile("cp.async.cg.shared.global [%0], [%1], 16;\n" :: "r"(s), "l"(gmem_src));
}
__device__ __forceinline__ float rnd_tf32(float f) {
    uint32_t u;
    asm("cvt.rna.tf32.f32 %0, %1;" : "=r"(u) : "f"(f));
    return __uint_as_float(u);
}
__device__ __forceinline__ void mma_tf32(float* d, const uint32_t* a, const uint32_t* b) {
    asm volatile(
        "mma.sync.aligned.m16n8k8.row.col.f32.tf32.tf32.f32 "
        "{%0,%1,%2,%3}, {%4,%5,%6,%7}, {%8,%9}, {%0,%1,%2,%3};"
        : "+f"(d[0]), "+f"(d[1]), "+f"(d[2]), "+f"(d[3])
        : "r"(a[0]), "r"(a[1]), "r"(a[2]), "r"(a[3]), "r"(b[0]), "r"(b[1]));
}
__device__ __forceinline__ void ldsm4(uint32_t* d, uint32_t addr) {
    asm volatile("ldmatrix.sync.aligned.m8n8.x4.shared.b16 {%0,%1,%2,%3}, [%4];"
        : "=r"(d[0]), "=r"(d[1]), "=r"(d[2]), "=r"(d[3]) : "r"(addr));
}
__device__ __forceinline__ int swz(int row, int ck) {
    return (ck & ~7) | ((ck ^ row) & 7);
}
__device__ __forceinline__ uint32_t smem_u32(const void* p) {
    return (uint32_t)__cvta_generic_to_shared(p);
}

// ---------------------------------------------------------------------------
// elementwise tf32 pre-round kernels
// ---------------------------------------------------------------------------
__global__ __launch_bounds__(256)
void round_tf32_kernel(const float* __restrict__ in, float* __restrict__ out, int n4)
{
    int i = blockIdx.x * blockDim.x + threadIdx.x;
    if (i < n4) {
        float4 v = ((const float4*)in)[i];
        v.x = rnd_tf32(v.x); v.y = rnd_tf32(v.y);
        v.z = rnd_tf32(v.z); v.w = rnd_tf32(v.w);
        ((float4*)out)[i] = v;
    }
}

__global__ __launch_bounds__(256)
void round_w4_kernel(const float* __restrict__ w0, const float* __restrict__ w1,
                     const float* __restrict__ w2, const float* __restrict__ w3,
                     float* __restrict__ out, int n4each)
{
    int i = blockIdx.x * blockDim.x + threadIdx.x;
    int which = i / n4each;
    int j = i - which * n4each;
    const float* src = (which == 0) ? w0 : (which == 1) ? w1 : (which == 2) ? w2 : w3;
    float4 v = ((const float4*)src)[j];
    v.x = rnd_tf32(v.x); v.y = rnd_tf32(v.y);
    v.z = rnd_tf32(v.z); v.w = rnd_tf32(v.w);
    ((float4*)out)[i] = v;
}

__global__ __launch_bounds__(256)
void concat_bias_kernel(const float* __restrict__ bq, const float* __restrict__ bk,
                        const float* __restrict__ bv, float* __restrict__ out)
{
    int i = blockIdx.x * blockDim.x + threadIdx.x; // 0..6143
    const float* s = (i < HID) ? bq : (i < 2 * HID) ? bk : bv;
    out[i] = s[i & (HID - 1)];
}

#define BK 32
#define NKT (HID / BK)   // 64

// ---------------------------------------------------------------------------
// Merged QKV tf32 GEMM, tile 128m x 96n (wave-quantized: 2048 CTAs).
// 8 warps = 4m x 2n, warp tile 32m x 48n. 2-stage, issue-before-wait.
// Stage: A 4096 + B 3072 floats = 28 KB; x2 = 56 KB.
// ---------------------------------------------------------------------------
#define QKV_BN 96
#define QKV_STAGE 7168
#define QKV_SMEM_BYTES (2 * QKV_STAGE * 4)

__global__ __launch_bounds__(256, 2)
void gemm_qkv_kernel(const float* __restrict__ A,
                     const float* __restrict__ Wcat,
                     float* __restrict__ qout,
                     float* __restrict__ kout,
                     float* __restrict__ vout)
{
    extern __shared__ float sm[];
    const int t    = threadIdx.x;
    const int lane = t & 31;
    const int wid  = t >> 5;
    const int wm   = wid & 3;
    const int wn   = wid >> 2;
    const int m0   = blockIdx.y * 128;
    const int n0g  = blockIdx.x * QKV_BN;       // global n within 6144
    const int r = lane >> 2;
    const int c = lane & 3;

    const int lane7 = lane & 7;
    const int a_sel = (lane >> 4) & 1;
    const int a_i16 = ((lane >> 3) & 1) * 8;
    const int b_sel = (lane >> 3) & 1;
    const int b_n8  = ((lane >> 4) & 1) * 8;

    const int a_ro0 = (wm * 32 + a_i16 + lane7) * 128;
    const int a_ro1 = a_ro0 + 16 * 128;
    int b_ro[3];
#pragma unroll
    for (int jp = 0; jp < 3; jp++)
        b_ro[jp] = (wn * 48 + jp * 16 + b_n8 + lane7) * 128;

    float acc[2][6][4];
#pragma unroll
    for (int i = 0; i < 2; i++)
#pragma unroll
        for (int j = 0; j < 6; j++)
#pragma unroll
            for (int e = 0; e < 4; e++) acc[i][j][e] = 0.f;

    auto issue_tile = [&](int kt, int buf) {
        float* As = sm + buf * QKV_STAGE;
        float* Ws = As + 4096;
        const int k0 = kt * BK;
#pragma unroll
        for (int i = 0; i < 4; i++) {          // A: 128 rows x 8 chunks
            int id  = t + i * 256;
            int row = id >> 3;
            int ck  = id & 7;
            int swk = (ck ^ (row & 7)) << 2;
            cp_async16(As + row * 32 + swk,
                       A + (size_t)(m0 + row) * HID + k0 + ck * 4);
        }
#pragma unroll
        for (int i = 0; i < 3; i++) {          // B: 96 rows x 8 chunks
            int id  = t + i * 256;
            int row = id >> 3;
            int ck  = id & 7;
            int swk = (ck ^ (row & 7)) << 2;
            cp_async16(Ws + row * 32 + swk,
                       Wcat + (size_t)(n0g + row) * HID + k0 + ck * 4);
        }
        asm volatile("cp.async.commit_group;\n");
    };

    issue_tile(0, 0);
    const uint32_t smbase = smem_u32(sm);

    for (int kt = 0; kt < NKT; kt++) {
        if (kt + 1 < NKT) {
            issue_tile(kt + 1, (kt + 1) & 1);
            asm volatile("cp.async.wait_group 1;\n");
        } else {
            asm volatile("cp.async.wait_group 0;\n");
        }
        __syncthreads();

        const uint32_t smA = smbase + (kt & 1) * (QKV_STAGE * 4);
        const uint32_t smB = smA + 16384;

#pragma unroll
        for (int ks = 0; ks < 4; ks++) {
            const int ea = (((2 * ks + a_sel) ^ lane7) << 4);
            const int eb = (((2 * ks + b_sel) ^ lane7) << 4);
            uint32_t af0[4], af1[4];
            ldsm4(af0, smA + a_ro0 + ea);
            ldsm4(af1, smA + a_ro1 + ea);
#pragma unroll
            for (int jp = 0; jp < 3; jp++) {
                uint32_t bf[4];
                ldsm4(bf, smB + b_ro[jp] + eb);
                mma_tf32(acc[0][2 * jp],     af0, &bf[0]);
                mma_tf32(acc[0][2 * jp + 1], af0, &bf[2]);
                mma_tf32(acc[1][2 * jp],     af1, &bf[0]);
                mma_tf32(acc[1][2 * jp + 1], af1, &bf[2]);
            }
        }
        __syncthreads();
    }

#pragma unroll
    for (int i = 0; i < 2; i++) {
        int r0 = m0 + wm * 32 + i * 16 + r;
        int r1 = r0 + 8;
        int b_0 = r0 >> 11, s_0 = r0 & 2047;
        int b_1 = r1 >> 11, s_1 = r1 & 2047;
#pragma unroll
        for (int j = 0; j < 6; j++) {
            int nbg = n0g + wn * 48 + j * 8 + 2 * c;   // global n (bias)
            int nb  = nbg & 2047;                      // within matrix
            int mat = nbg >> 11;                       // 0=Q 1=K 2=V
            float b0 = g_bqkv[nbg], b1 = g_bqkv[nbg + 1];
            float d00 = rnd_tf32(acc[i][j][0] + b0);
            float d01 = rnd_tf32(acc[i][j][1] + b1);
            float d10 = rnd_tf32(acc[i][j][2] + b0);
            float d11 = rnd_tf32(acc[i][j][3] + b1);
            int h = nb >> 7, d = nb & 127;
            if (mat < 2) {
                float* outQK = (mat == 0) ? qout : kout;
                *(float2*)&outQK[(size_t)((b_0 * NHEAD + h) * SEQ + s_0) * HDIM + d] =
                    make_float2(d00, d01);
                *(float2*)&outQK[(size_t)((b_1 * NHEAD + h) * SEQ + s_1) * HDIM + d] =
                    make_float2(d10, d11);
            } else {
                size_t base0 = (size_t)((b_0 * NHEAD + h) * HDIM + d) * SEQ;
                size_t base1 = (size_t)((b_1 * NHEAD + h) * HDIM + d) * SEQ;
                vout[base0 + s_0]       = d00;
                vout[base0 + SEQ + s_0] = d01;
                vout[base1 + s_1]       = d10;
                vout[base1 + SEQ + s_1] = d11;
            }
        }
    }
}

// ---------------------------------------------------------------------------
// O-projection GEMM (row-major fp32 out), 128x128 tile — r7 structure.
// ---------------------------------------------------------------------------
#define BUF_FLOATS 8192

__global__ __launch_bounds__(256, 2)
void gemm_o_kernel(const float* __restrict__ A,
                   const float* __restrict__ W,
                   const float* __restrict__ bias,
                   float* __restrict__ out)
{
    extern __shared__ float sm[];
    const int t    = threadIdx.x;
    const int lane = t & 31;
    const int wid  = t >> 5;
    const int wm   = wid & 3;
    const int wn   = wid >> 2;
    const int m0   = blockIdx.y * 128;
    const int n0   = blockIdx.x * 128;
    const int r = lane >> 2;
    const int c = lane & 3;

    const int lane7 = lane & 7;
    const int a_sel = (lane >> 4) & 1;
    const int a_i16 = ((lane >> 3) & 1) * 8;
    const int b_sel = (lane >> 3) & 1;
    const int b_n8  = ((lane >> 4) & 1) * 8;

    const int a_ro0 = (wm * 32 + a_i16 + lane7) * 128;
    const int a_ro1 = a_ro0 + 16 * 128;
    int b_ro[4];
#pragma unroll
    for (int jp = 0; jp < 4; jp++)
        b_ro[jp] = (wn * 64 + jp * 16 + b_n8 + lane7) * 128;

    float acc[2][8][4];
#pragma unroll
    for (int i = 0; i < 2; i++)
#pragma unroll
        for (int j = 0; j < 8; j++)
#pragma unroll
            for (int e = 0; e < 4; e++) acc[i][j][e] = 0.f;

    auto issue_tile = [&](int kt, int buf) {
        float* As = sm + buf * BUF_FLOATS;
        float* Ws = As + 4096;
        const int k0 = kt * BK;
#pragma unroll
        for (int i = 0; i < 4; i++) {
            int id  = t + i * 256;
            int row = id >> 3;
            int ck  = id & 7;
            int swk = (ck ^ (row & 7)) << 2;
            cp_async16(As + row * 32 + swk,
                       A + (size_t)(m0 + row) * HID + k0 + ck * 4);
            cp_async16(Ws + row * 32 + swk,
                       W + (size_t)(n0 + row) * HID + k0 + ck * 4);
        }
        asm volatile("cp.async.commit_group;\n");
    };

    issue_tile(0, 0);
    const uint32_t smbase = smem_u32(sm);

    for (int kt = 0; kt < NKT; kt++) {
        if (kt + 1 < NKT) {
            issue_tile(kt + 1, (kt + 1) & 1);
            asm volatile("cp.async.wait_group 1;\n");
        } else {
            asm volatile("cp.async.wait_group 0;\n");
        }
        __syncthreads();

        const uint32_t smA = smbase + (kt & 1) * (BUF_FLOATS * 4);
        const uint32_t smB = smA + 16384;

#pragma unroll
        for (int ks = 0; ks < 4; ks++) {
            const int ea = (((2 * ks + a_sel) ^ lane7) << 4);
            const int eb = (((2 * ks + b_sel) ^ lane7) << 4);
            uint32_t af0[4], af1[4];
            ldsm4(af0, smA + a_ro0 + ea);
            ldsm4(af1, smA + a_ro1 + ea);
#pragma unroll
            for (int jp = 0; jp < 4; jp++) {
                uint32_t bf[4];
                ldsm4(bf, smB + b_ro[jp] + eb);
                mma_tf32(acc[0][2 * jp],     af0, &bf[0]);
                mma_tf32(acc[0][2 * jp + 1], af0, &bf[2]);
                mma_tf32(acc[1][2 * jp],     af1, &bf[0]);
                mma_tf32(acc[1][2 * jp + 1], af1, &bf[2]);
            }
        }
        __syncthreads();
    }

#pragma unroll
    for (int i = 0; i < 2; i++) {
        int r0 = m0 + wm * 32 + i * 16 + r;
        int r1 = r0 + 8;
#pragma unroll
        for (int j = 0; j < 8; j++) {
            int nb = n0 + wn * 64 + j * 8 + 2 * c;
            float b0 = bias[nb], b1 = bias[nb + 1];
            *(float2*)&out[(size_t)r0 * HID + nb] =
                make_float2(acc[i][j][0] + b0, acc[i][j][1] + b1);
            *(float2*)&out[(size_t)r1 * HID + nb] =
                make_float2(acc[i][j][2] + b0, acc[i][j][3] + b1);
        }
    }
}

// ---------------------------------------------------------------------------
// Flash attention — exact round-9 structure (measured best).
// 128-thread CTAs, q-tile 64, single-buffered KV, 2 CTAs/SM.
// smem: Q 8192 | K 8192 | V 8192 | P 4096 floats = 112 KB
// ---------------------------------------------------------------------------
#define AQ_OFF 0
#define AK_OFF 8192
#define AV_OFF 16384
#define AP_OFF 24576
#define ATTN_SMEM_FLOATS 28672   // 114688 bytes

__global__ __launch_bounds__(128, 2)
void attn_tc_kernel()
{
    extern __shared__ float sm[];
    float* Ps = sm + AP_OFF;

    const int t    = threadIdx.x;
    const int lane = t & 31;
    const int w    = t >> 5;       // 0..3
    const int r    = lane >> 2;
    const int c    = lane & 3;
    const int qbI  = 31 - blockIdx.x;   // heavy tiles first
    const int bh   = blockIdx.y;
    const int q0   = qbI * 64;
    const int nkb  = qbI + 1;
    const float scale = 0.08838834764831845f; // 1/sqrt(128)

    const int lane7 = lane & 7;
    const int a_sel = (lane >> 4) & 1;
    const int a_i16 = ((lane >> 3) & 1) * 8;
    const int b_sel = (lane >> 3) & 1;
    const int b_n8  = ((lane >> 4) & 1) * 8;

    const float* Qg = g_Q  + (size_t)bh * SEQ * HDIM;
    const float* Kg = g_K  + (size_t)bh * SEQ * HDIM;
    const float* Vg = g_Vt + (size_t)bh * HDIM * SEQ;

    const uint32_t smu  = smem_u32(sm);
    const uint32_t Qs_u = smu + AQ_OFF * 4;
    const uint32_t Ks_u = smu + AK_OFF * 4;
    const uint32_t Vs_u = smu + AV_OFF * 4;
    const uint32_t Ps_u = smu + AP_OFF * 4;

    const int a_roQ = (w * 16 + a_i16 + lane7) * 512;
    const int a_roP = (w * 16 + a_i16 + lane7) * 256;
    int b_roK[4];
#pragma unroll
    for (int jp = 0; jp < 4; jp++)
        b_roK[jp] = (jp * 16 + b_n8 + lane7) * 512;
    int b_roV[8];
#pragma unroll
    for (int jp = 0; jp < 8; jp++)
        b_roV[jp] = (jp * 16 + b_n8 + lane7) * 256;

    auto issueKV = [&](int kb) {
        const int k0 = kb * 64;
#pragma unroll
        for (int i = 0; i < 16; i++) {       // K: 64 rows x 32 chunks
            int id = t + i * 128;
            int row = id >> 5, ck = id & 31;
            cp_async16(sm + AK_OFF + row * 128 + swz(row & 7, ck) * 4,
                       Kg + (size_t)(k0 + row) * HDIM + ck * 4);
        }
#pragma unroll
        for (int i = 0; i < 16; i++) {       // V: 128 d-rows x 16 chunks
            int id = t + i * 128;
            int row = id >> 4, ck = id & 15;
            cp_async16(sm + AV_OFF + row * 64 + swz(row & 7, ck) * 4,
                       Vg + (size_t)row * SEQ + k0 + ck * 4);
        }
        asm volatile("cp.async.commit_group;\n");
    };

    // prologue: Q (once) + KV(0)
#pragma unroll
    for (int i = 0; i < 16; i++) {
        int id = t + i * 128;
        int row = id >> 5, ck = id & 31;
        cp_async16(sm + AQ_OFF + row * 128 + swz(row & 7, ck) * 4,
                   Qg + (size_t)(q0 + row) * HDIM + ck * 4);
    }
    issueKV(0);
    asm volatile("cp.async.wait_group 0;\n");
    __syncthreads();

    float m_s[2], l_s[2], O[16][4];
#pragma unroll
    for (int e = 0; e < 2; e++) { m_s[e] = -1e30f; l_s[e] = 0.f; }
#pragma unroll
    for (int j = 0; j < 16; j++)
#pragma unroll
        for (int e = 0; e < 4; e++) O[j][e] = 0.f;

    const int qrow = w * 16 + r;

    for (int kb = 0; kb < nkb; kb++) {
        const int k0 = kb * 64;

        // ---- S = Q K^T ----
        float sacc[8][4];
#pragma unroll
        for (int j = 0; j < 8; j++)
#pragma unroll
            for (int e = 0; e < 4; e++) sacc[j][e] = 0.f;

#pragma unroll
        for (int ks = 0; ks < 16; ks++) {
            const int ea = swz(lane7, 2 * ks + a_sel) << 4;
            const int eb = swz(lane7, 2 * ks + b_sel) << 4;
            uint32_t a[4];
            ldsm4(a, Qs_u + a_roQ + ea);
#pragma unroll
            for (int jp = 0; jp < 4; jp++) {
                uint32_t bf[4];
                ldsm4(bf, Ks_u + b_roK[jp] + eb);
                mma_tf32(sacc[2 * jp],     a, &bf[0]);
                mma_tf32(sacc[2 * jp + 1], a, &bf[2]);
            }
        }

        // ---- scale + causal mask ----
        const bool need_mask = (kb == nkb - 1);
#pragma unroll
        for (int j = 0; j < 8; j++)
#pragma unroll
            for (int e = 0; e < 4; e++) {
                float v = sacc[j][e] * scale;
                if (need_mask) {
                    int col = k0 + j * 8 + 2 * c + (e & 1);
                    int row = q0 + qrow + ((e & 2) ? 8 : 0);
                    if (col > row) v = -1e30f;
                }
                sacc[j][e] = v;
            }

        // ---- online softmax ----
#pragma unroll
        for (int half = 0; half < 2; half++) {
            const int e0 = half * 2;
            float rmax = -1e30f;
#pragma unroll
            for (int j = 0; j < 8; j++)
                rmax = fmaxf(rmax, fmaxf(sacc[j][e0], sacc[j][e0 + 1]));
            rmax = fmaxf(rmax, __shfl_xor_sync(0xffffffffu, rmax, 1));
            rmax = fmaxf(rmax, __shfl_xor_sync(0xffffffffu, rmax, 2));
            float mnew = fmaxf(m_s[half], rmax);
            float corr = __expf(m_s[half] - mnew);
            float rsum = 0.f;
#pragma unroll
            for (int j = 0; j < 8; j++) {
                float p0 = __expf(sacc[j][e0] - mnew);
                float p1 = __expf(sacc[j][e0 + 1] - mnew);
                sacc[j][e0] = p0; sacc[j][e0 + 1] = p1;
                rsum += p0 + p1;
            }
            rsum += __shfl_xor_sync(0xffffffffu, rsum, 1);
            rsum += __shfl_xor_sync(0xffffffffu, rsum, 2);
            l_s[half] = l_s[half] * corr + rsum;
            m_s[half] = mnew;
#pragma unroll
            for (int j = 0; j < 16; j++) {
                O[j][e0]     *= corr;
                O[j][e0 + 1] *= corr;
            }
        }

        // ---- P -> smem (tf32-rounded, per-warp region) ----
#pragma unroll
        for (int j = 0; j < 8; j++) {
            int ck = 2 * j + (c >> 1);
            int off = swz(r, ck) * 4 + (c & 1) * 2;
            *(float2*)&Ps[qrow * 64 + off] =
                make_float2(rnd_tf32(sacc[j][0]), rnd_tf32(sacc[j][1]));
            *(float2*)&Ps[(qrow + 8) * 64 + off] =
                make_float2(rnd_tf32(sacc[j][2]), rnd_tf32(sacc[j][3]));
        }
        __syncwarp();

        // ---- O += P V ----
#pragma unroll
        for (int ks = 0; ks < 8; ks++) {
            const int ea = swz(lane7, 2 * ks + a_sel) << 4;
            const int eb = swz(lane7, 2 * ks + b_sel) << 4;
            uint32_t a[4];
            ldsm4(a, Ps_u + a_roP + ea);
#pragma unroll
            for (int jp = 0; jp < 8; jp++) {
                uint32_t bf[4];
                ldsm4(bf, Vs_u + b_roV[jp] + eb);
                mma_tf32(O[2 * jp],     a, &bf[0]);
                mma_tf32(O[2 * jp + 1], a, &bf[2]);
            }
        }

        // ---- refill single KV buffer ----
        if (kb + 1 < nkb) {
            __syncthreads();
            issueKV(kb + 1);
            asm volatile("cp.async.wait_group 0;\n");
            __syncthreads();
        }
    }

    const int b = bh >> 4, h = bh & 15;
    const float inv0 = 1.f / l_s[0];
    const float inv1 = 1.f / l_s[1];
    const int row0 = q0 + qrow, row1 = row0 + 8;
#pragma unroll
    for (int j = 0; j < 16; j++) {
        int n = h * HDIM + j * 8 + 2 * c;
        *(float2*)&g_attn[(size_t)(b * SEQ + row0) * HID + n] =
            make_float2(rnd_tf32(O[j][0] * inv0), rnd_tf32(O[j][1] * inv0));
        *(float2*)&g_attn[(size_t)(b * SEQ + row1) * HID + n] =
            make_float2(rnd_tf32(O[j][2] * inv1), rnd_tf32(O[j][3] * inv1));
    }
}

// ---------------------------------------------------------------------------
extern "C" void kernel_launch(void* const* d_in, const int* in_sizes, int n_in,
                              void* d_out, int out_size)
{
    const float* x  = (const float*)d_in[0];
    const float* Wq = (const float*)d_in[1];
    const float* bq = (const float*)d_in[2];
    const float* Wk = (const float*)d_in[3];
    const float* bk = (const float*)d_in[4];
    const float* Wv = (const float*)d_in[5];
    const float* bv = (const float*)d_in[6];
    const float* Wo = (const float*)d_in[7];
    const float* bo = (const float*)d_in[8];
    float* out = (float*)d_out;

    float *q, *k, *vt, *attn, *xr, *wr, *bcat;
    cudaGetSymbolAddress((void**)&q,    g_Q);
    cudaGetSymbolAddress((void**)&k,    g_K);
    cudaGetSymbolAddress((void**)&vt,   g_Vt);
    cudaGetSymbolAddress((void**)&attn, g_attn);
    cudaGetSymbolAddress((void**)&xr,   g_xr);
    cudaGetSymbolAddress((void**)&wr,   g_Wr);
    cudaGetSymbolAddress((void**)&bcat, g_bqkv);

    cudaFuncSetAttribute(gemm_qkv_kernel,
                         cudaFuncAttributeMaxDynamicSharedMemorySize, QKV_SMEM_BYTES);
    const size_t gemm_smem = BUF_FLOATS * 2 * sizeof(float);        // 64 KB
    cudaFuncSetAttribute(gemm_o_kernel,
                         cudaFuncAttributeMaxDynamicSharedMemorySize, (int)gemm_smem);
    const size_t attn_smem = ATTN_SMEM_FLOATS * sizeof(float);      // 112 KB
    cudaFuncSetAttribute(attn_tc_kernel,
                         cudaFuncAttributeMaxDynamicSharedMemorySize, (int)attn_smem);

    const int NX4 = MROWS * HID / 4;
    const int NW4 = HID * HID / 4;
    float* wo_r = wr + 3ull * HID * HID;

    round_tf32_kernel<<<NX4 / 256, 256>>>(x, xr, NX4);
    round_w4_kernel<<<4 * NW4 / 256, 256>>>(Wq, Wk, Wv, Wo, wr, NW4);
    concat_bias_kernel<<<3 * HID / 256, 256>>>(bq, bk, bv, bcat);

    gemm_qkv_kernel<<<dim3(3 * HID / QKV_BN, MROWS / 128), 256, QKV_SMEM_BYTES>>>(
        xr, wr, q, k, vt);                      // grid (64, 32)
    attn_tc_kernel<<<dim3(SEQ / 64, BH), 128, attn_smem>>>();
    gemm_o_kernel<<<dim3(HID / 128, MROWS / 128), 256, gemm_smem>>>(
        attn, wo_r, bo, out);
}

// round 12
// speedup vs baseline: 1.0264x; 1.0264x over previous
#include <cuda_runtime.h>
#include <cstdint>

#define HID   2048
#define MROWS 4096   // B*S
#define NHEAD 16
#define HDIM  128
#define SEQ   2048
#define BH    32     // B*NHEAD

// Scratch (no allocations allowed)
__device__ float g_Q [BH * SEQ * HDIM];       // [bh][s][d]   (tf32-rounded)
__device__ float g_K [BH * SEQ * HDIM];       // [bh][s][d]   (tf32-rounded)
__device__ float g_Vt[BH * HDIM * SEQ];       // [bh][d][s]   (tf32-rounded)
__device__ float g_attn[(size_t)MROWS * HID]; // [B*S][nh*hd] (tf32-rounded)
__device__ float g_xr[(size_t)MROWS * HID];   // rounded x
__device__ float g_Wr[4ull * HID * HID];      // rounded Wq,Wk,Wv,Wo (contiguous)
__device__ float g_bqkv[3 * HID];             // concat bq|bk|bv

// ---------------------------------------------------------------------------
// helpers
// ---------------------------------------------------------------------------
__device__ __forceinline__ void cp_async16(void* smem_dst, const void* gmem_src) {
    uint32_t s = (uint32_t)__cvta_generic_to_shared(smem_dst);
    asm volatile("cp.async.cg.shared.global [%0], [%1], 16;\n" :: "r"(s), "l"(gmem_src));
}
__device__ __forceinline__ float rnd_tf32(float f) {
    uint32_t u;
    asm("cvt.rna.tf32.f32 %0, %1;" : "=r"(u) : "f"(f));
    return __uint_as_float(u);
}
__device__ __forceinline__ void mma_tf32(float* d, const uint32_t* a, const uint32_t* b) {
    asm volatile(
        "mma.sync.aligned.m16n8k8.row.col.f32.tf32.tf32.f32 "
        "{%0,%1,%2,%3}, {%4,%5,%6,%7}, {%8,%9}, {%0,%1,%2,%3};"
        : "+f"(d[0]), "+f"(d[1]), "+f"(d[2]), "+f"(d[3])
        : "r"(a[0]), "r"(a[1]), "r"(a[2]), "r"(a[3]), "r"(b[0]), "r"(b[1]));
}
__device__ __forceinline__ void ldsm4(uint32_t* d, uint32_t addr) {
    asm volatile("ldmatrix.sync.aligned.m8n8.x4.shared.b16 {%0,%1,%2,%3}, [%4];"
        : "=r"(d[0]), "=r"(d[1]), "=r"(d[2]), "=r"(d[3]) : "r"(addr));
}
__device__ __forceinline__ int swz(int row, int ck) {
    return (ck & ~7) | ((ck ^ row) & 7);
}
__device__ __forceinline__ uint32_t smem_u32(const void* p) {
    return (uint32_t)__cvta_generic_to_shared(p);
}

// ---------------------------------------------------------------------------
// Fused prologue: tf32-round x and all 4 weights, concat biases.
// Regions (float4 units): x = 2,097,152 (blocks [0, 8192));
// each W = 1,048,576 (blocks [8192 + 4096*w, ...)). Blocks 0..23 also
// handle the 6144-element bias concat.
// ---------------------------------------------------------------------------
__global__ __launch_bounds__(256)
void prep_kernel(const float* __restrict__ x,
                 const float* __restrict__ w0, const float* __restrict__ w1,
                 const float* __restrict__ w2, const float* __restrict__ w3,
                 const float* __restrict__ bq, const float* __restrict__ bk,
                 const float* __restrict__ bv,
                 float* __restrict__ xr, float* __restrict__ wr,
                 float* __restrict__ bcat)
{
    const int blk = blockIdx.x;
    const int tid = threadIdx.x;

    // bias concat (first 24 blocks, 6144 elements)
    int bi = blk * 256 + tid;
    if (bi < 3 * HID) {
        const float* s = (bi < HID) ? bq : (bi < 2 * HID) ? bk : bv;
        bcat[bi] = s[bi & (HID - 1)];
    }

    const float4* src;
    float4* dst;
    int idx;
    if (blk < 8192) {                       // x region
        idx = blk * 256 + tid;
        src = (const float4*)x;
        dst = (float4*)xr;
    } else {                                // weight regions
        int wb = blk - 8192;
        int which = wb >> 12;               // /4096
        idx = (wb & 4095) * 256 + tid;
        src = (const float4*)((which == 0) ? w0 : (which == 1) ? w1 :
                              (which == 2) ? w2 : w3);
        dst = (float4*)(wr + (size_t)which * HID * HID);
    }
    float4 v = src[idx];
    v.x = rnd_tf32(v.x); v.y = rnd_tf32(v.y);
    v.z = rnd_tf32(v.z); v.w = rnd_tf32(v.w);
    dst[idx] = v;
}

// ---------------------------------------------------------------------------
// GEMMs: exact round-7 structure (2-stage, issue-before-wait, two syncs).
// ---------------------------------------------------------------------------
#define BK 32
#define NKT (HID / BK)   // 64
#define BUF_FLOATS 8192

__global__ __launch_bounds__(256, 2)
void gemm_qkv_kernel(const float* __restrict__ A,
                     const float* __restrict__ Wcat,
                     float* __restrict__ qout,
                     float* __restrict__ kout,
                     float* __restrict__ vout)
{
    extern __shared__ float sm[];
    const int t    = threadIdx.x;
    const int lane = t & 31;
    const int wid  = t >> 5;
    const int wm   = wid & 3;
    const int wn   = wid >> 2;
    const int m0   = blockIdx.y * 128;
    const int n0g  = blockIdx.x * 128;
    const int mat  = blockIdx.x >> 4;          // 0=Q 1=K 2=V
    const int r = lane >> 2;
    const int c = lane & 3;

    const int lane7 = lane & 7;
    const int a_sel = (lane >> 4) & 1;
    const int a_i16 = ((lane >> 3) & 1) * 8;
    const int b_sel = (lane >> 3) & 1;
    const int b_n8  = ((lane >> 4) & 1) * 8;

    const int a_ro0 = (wm * 32 + a_i16 + lane7) * 128;
    const int a_ro1 = a_ro0 + 16 * 128;
    int b_ro[4];
#pragma unroll
    for (int jp = 0; jp < 4; jp++)
        b_ro[jp] = (wn * 64 + jp * 16 + b_n8 + lane7) * 128;

    float acc[2][8][4];
#pragma unroll
    for (int i = 0; i < 2; i++)
#pragma unroll
        for (int j = 0; j < 8; j++)
#pragma unroll
            for (int e = 0; e < 4; e++) acc[i][j][e] = 0.f;

    auto issue_tile = [&](int kt, int buf) {
        float* As = sm + buf * BUF_FLOATS;
        float* Ws = As + 4096;
        const int k0 = kt * BK;
#pragma unroll
        for (int i = 0; i < 4; i++) {
            int id  = t + i * 256;
            int row = id >> 3;
            int ck  = id & 7;
            int swk = (ck ^ (row & 7)) << 2;
            cp_async16(As + row * 32 + swk,
                       A + (size_t)(m0 + row) * HID + k0 + ck * 4);
            cp_async16(Ws + row * 32 + swk,
                       Wcat + (size_t)(n0g + row) * HID + k0 + ck * 4);
        }
        asm volatile("cp.async.commit_group;\n");
    };

    issue_tile(0, 0);
    const uint32_t smbase = smem_u32(sm);

    for (int kt = 0; kt < NKT; kt++) {
        if (kt + 1 < NKT) {
            issue_tile(kt + 1, (kt + 1) & 1);
            asm volatile("cp.async.wait_group 1;\n");
        } else {
            asm volatile("cp.async.wait_group 0;\n");
        }
        __syncthreads();

        const uint32_t smA = smbase + (kt & 1) * (BUF_FLOATS * 4);
        const uint32_t smB = smA + 16384;

#pragma unroll
        for (int ks = 0; ks < 4; ks++) {
            const int ea = (((2 * ks + a_sel) ^ lane7) << 4);
            const int eb = (((2 * ks + b_sel) ^ lane7) << 4);
            uint32_t af0[4], af1[4];
            ldsm4(af0, smA + a_ro0 + ea);
            ldsm4(af1, smA + a_ro1 + ea);
#pragma unroll
            for (int jp = 0; jp < 4; jp++) {
                uint32_t bf[4];
                ldsm4(bf, smB + b_ro[jp] + eb);
                mma_tf32(acc[0][2 * jp],     af0, &bf[0]);
                mma_tf32(acc[0][2 * jp + 1], af0, &bf[2]);
                mma_tf32(acc[1][2 * jp],     af1, &bf[0]);
                mma_tf32(acc[1][2 * jp + 1], af1, &bf[2]);
            }
        }
        __syncthreads();
    }

    float* outQK = (mat == 0) ? qout : kout;

#pragma unroll
    for (int i = 0; i < 2; i++) {
        int r0 = m0 + wm * 32 + i * 16 + r;
        int r1 = r0 + 8;
        int b_0 = r0 >> 11, s_0 = r0 & 2047;
        int b_1 = r1 >> 11, s_1 = r1 & 2047;
#pragma unroll
        for (int j = 0; j < 8; j++) {
            int nbg = n0g + wn * 64 + j * 8 + 2 * c;
            int nb  = nbg & 2047;
            float b0 = g_bqkv[nbg], b1 = g_bqkv[nbg + 1];
            float d00 = rnd_tf32(acc[i][j][0] + b0);
            float d01 = rnd_tf32(acc[i][j][1] + b1);
            float d10 = rnd_tf32(acc[i][j][2] + b0);
            float d11 = rnd_tf32(acc[i][j][3] + b1);
            int h = nb >> 7, d = nb & 127;
            if (mat < 2) {
                *(float2*)&outQK[(size_t)((b_0 * NHEAD + h) * SEQ + s_0) * HDIM + d] =
                    make_float2(d00, d01);
                *(float2*)&outQK[(size_t)((b_1 * NHEAD + h) * SEQ + s_1) * HDIM + d] =
                    make_float2(d10, d11);
            } else {
                size_t base0 = (size_t)((b_0 * NHEAD + h) * HDIM + d) * SEQ;
                size_t base1 = (size_t)((b_1 * NHEAD + h) * HDIM + d) * SEQ;
                vout[base0 + s_0]       = d00;
                vout[base0 + SEQ + s_0] = d01;
                vout[base1 + s_1]       = d10;
                vout[base1 + SEQ + s_1] = d11;
            }
        }
    }
}

__global__ __launch_bounds__(256, 2)
void gemm_o_kernel(const float* __restrict__ A,
                   const float* __restrict__ W,
                   const float* __restrict__ bias,
                   float* __restrict__ out)
{
    extern __shared__ float sm[];
    const int t    = threadIdx.x;
    const int lane = t & 31;
    const int wid  = t >> 5;
    const int wm   = wid & 3;
    const int wn   = wid >> 2;
    const int m0   = blockIdx.y * 128;
    const int n0   = blockIdx.x * 128;
    const int r = lane >> 2;
    const int c = lane & 3;

    const int lane7 = lane & 7;
    const int a_sel = (lane >> 4) & 1;
    const int a_i16 = ((lane >> 3) & 1) * 8;
    const int b_sel = (lane >> 3) & 1;
    const int b_n8  = ((lane >> 4) & 1) * 8;

    const int a_ro0 = (wm * 32 + a_i16 + lane7) * 128;
    const int a_ro1 = a_ro0 + 16 * 128;
    int b_ro[4];
#pragma unroll
    for (int jp = 0; jp < 4; jp++)
        b_ro[jp] = (wn * 64 + jp * 16 + b_n8 + lane7) * 128;

    float acc[2][8][4];
#pragma unroll
    for (int i = 0; i < 2; i++)
#pragma unroll
        for (int j = 0; j < 8; j++)
#pragma unroll
            for (int e = 0; e < 4; e++) acc[i][j][e] = 0.f;

    auto issue_tile = [&](int kt, int buf) {
        float* As = sm + buf * BUF_FLOATS;
        float* Ws = As + 4096;
        const int k0 = kt * BK;
#pragma unroll
        for (int i = 0; i < 4; i++) {
            int id  = t + i * 256;
            int row = id >> 3;
            int ck  = id & 7;
            int swk = (ck ^ (row & 7)) << 2;
            cp_async16(As + row * 32 + swk,
                       A + (size_t)(m0 + row) * HID + k0 + ck * 4);
            cp_async16(Ws + row * 32 + swk,
                       W + (size_t)(n0 + row) * HID + k0 + ck * 4);
        }
        asm volatile("cp.async.commit_group;\n");
    };

    issue_tile(0, 0);
    const uint32_t smbase = smem_u32(sm);

    for (int kt = 0; kt < NKT; kt++) {
        if (kt + 1 < NKT) {
            issue_tile(kt + 1, (kt + 1) & 1);
            asm volatile("cp.async.wait_group 1;\n");
        } else {
            asm volatile("cp.async.wait_group 0;\n");
        }
        __syncthreads();

        const uint32_t smA = smbase + (kt & 1) * (BUF_FLOATS * 4);
        const uint32_t smB = smA + 16384;

#pragma unroll
        for (int ks = 0; ks < 4; ks++) {
            const int ea = (((2 * ks + a_sel) ^ lane7) << 4);
            const int eb = (((2 * ks + b_sel) ^ lane7) << 4);
            uint32_t af0[4], af1[4];
            ldsm4(af0, smA + a_ro0 + ea);
            ldsm4(af1, smA + a_ro1 + ea);
#pragma unroll
            for (int jp = 0; jp < 4; jp++) {
                uint32_t bf[4];
                ldsm4(bf, smB + b_ro[jp] + eb);
                mma_tf32(acc[0][2 * jp],     af0, &bf[0]);
                mma_tf32(acc[0][2 * jp + 1], af0, &bf[2]);
                mma_tf32(acc[1][2 * jp],     af1, &bf[0]);
                mma_tf32(acc[1][2 * jp + 1], af1, &bf[2]);
            }
        }
        __syncthreads();
    }

#pragma unroll
    for (int i = 0; i < 2; i++) {
        int r0 = m0 + wm * 32 + i * 16 + r;
        int r1 = r0 + 8;
#pragma unroll
        for (int j = 0; j < 8; j++) {
            int nb = n0 + wn * 64 + j * 8 + 2 * c;
            float b0 = bias[nb], b1 = bias[nb + 1];
            *(float2*)&out[(size_t)r0 * HID + nb] =
                make_float2(acc[i][j][0] + b0, acc[i][j][1] + b1);
            *(float2*)&out[(size_t)r1 * HID + nb] =
                make_float2(acc[i][j][2] + b0, acc[i][j][3] + b1);
        }
    }
}

// ---------------------------------------------------------------------------
// Flash attention — exact round-9 structure (measured best).
// 128-thread CTAs, q-tile 64, single-buffered KV, 2 CTAs/SM.
// smem: Q 8192 | K 8192 | V 8192 | P 4096 floats = 112 KB
// ---------------------------------------------------------------------------
#define AQ_OFF 0
#define AK_OFF 8192
#define AV_OFF 16384
#define AP_OFF 24576
#define ATTN_SMEM_FLOATS 28672   // 114688 bytes

__global__ __launch_bounds__(128, 2)
void attn_tc_kernel()
{
    extern __shared__ float sm[];
    float* Ps = sm + AP_OFF;

    const int t    = threadIdx.x;
    const int lane = t & 31;
    const int w    = t >> 5;       // 0..3
    const int r    = lane >> 2;
    const int c    = lane & 3;
    const int qbI  = 31 - blockIdx.x;   // heavy tiles first
    const int bh   = blockIdx.y;
    const int q0   = qbI * 64;
    const int nkb  = qbI + 1;
    const float scale = 0.08838834764831845f; // 1/sqrt(128)

    const int lane7 = lane & 7;
    const int a_sel = (lane >> 4) & 1;
    const int a_i16 = ((lane >> 3) & 1) * 8;
    const int b_sel = (lane >> 3) & 1;
    const int b_n8  = ((lane >> 4) & 1) * 8;

    const float* Qg = g_Q  + (size_t)bh * SEQ * HDIM;
    const float* Kg = g_K  + (size_t)bh * SEQ * HDIM;
    const float* Vg = g_Vt + (size_t)bh * HDIM * SEQ;

    const uint32_t smu  = smem_u32(sm);
    const uint32_t Qs_u = smu + AQ_OFF * 4;
    const uint32_t Ks_u = smu + AK_OFF * 4;
    const uint32_t Vs_u = smu + AV_OFF * 4;
    const uint32_t Ps_u = smu + AP_OFF * 4;

    const int a_roQ = (w * 16 + a_i16 + lane7) * 512;
    const int a_roP = (w * 16 + a_i16 + lane7) * 256;
    int b_roK[4];
#pragma unroll
    for (int jp = 0; jp < 4; jp++)
        b_roK[jp] = (jp * 16 + b_n8 + lane7) * 512;
    int b_roV[8];
#pragma unroll
    for (int jp = 0; jp < 8; jp++)
        b_roV[jp] = (jp * 16 + b_n8 + lane7) * 256;

    auto issueKV = [&](int kb) {
        const int k0 = kb * 64;
#pragma unroll
        for (int i = 0; i < 16; i++) {       // K: 64 rows x 32 chunks
            int id = t + i * 128;
            int row = id >> 5, ck = id & 31;
            cp_async16(sm + AK_OFF + row * 128 + swz(row & 7, ck) * 4,
                       Kg + (size_t)(k0 + row) * HDIM + ck * 4);
        }
#pragma unroll
        for (int i = 0; i < 16; i++) {       // V: 128 d-rows x 16 chunks
            int id = t + i * 128;
            int row = id >> 4, ck = id & 15;
            cp_async16(sm + AV_OFF + row * 64 + swz(row & 7, ck) * 4,
                       Vg + (size_t)row * SEQ + k0 + ck * 4);
        }
        asm volatile("cp.async.commit_group;\n");
    };

    // prologue: Q (once) + KV(0)
#pragma unroll
    for (int i = 0; i < 16; i++) {
        int id = t + i * 128;
        int row = id >> 5, ck = id & 31;
        cp_async16(sm + AQ_OFF + row * 128 + swz(row & 7, ck) * 4,
                   Qg + (size_t)(q0 + row) * HDIM + ck * 4);
    }
    issueKV(0);
    asm volatile("cp.async.wait_group 0;\n");
    __syncthreads();

    float m_s[2], l_s[2], O[16][4];
#pragma unroll
    for (int e = 0; e < 2; e++) { m_s[e] = -1e30f; l_s[e] = 0.f; }
#pragma unroll
    for (int j = 0; j < 16; j++)
#pragma unroll
        for (int e = 0; e < 4; e++) O[j][e] = 0.f;

    const int qrow = w * 16 + r;

    for (int kb = 0; kb < nkb; kb++) {
        const int k0 = kb * 64;

        // ---- S = Q K^T ----
        float sacc[8][4];
#pragma unroll
        for (int j = 0; j < 8; j++)
#pragma unroll
            for (int e = 0; e < 4; e++) sacc[j][e] = 0.f;

#pragma unroll
        for (int ks = 0; ks < 16; ks++) {
            const int ea = swz(lane7, 2 * ks + a_sel) << 4;
            const int eb = swz(lane7, 2 * ks + b_sel) << 4;
            uint32_t a[4];
            ldsm4(a, Qs_u + a_roQ + ea);
#pragma unroll
            for (int jp = 0; jp < 4; jp++) {
                uint32_t bf[4];
                ldsm4(bf, Ks_u + b_roK[jp] + eb);
                mma_tf32(sacc[2 * jp],     a, &bf[0]);
                mma_tf32(sacc[2 * jp + 1], a, &bf[2]);
            }
        }

        // ---- scale + causal mask ----
        const bool need_mask = (kb == nkb - 1);
#pragma unroll
        for (int j = 0; j < 8; j++)
#pragma unroll
            for (int e = 0; e < 4; e++) {
                float v = sacc[j][e] * scale;
                if (need_mask) {
                    int col = k0 + j * 8 + 2 * c + (e & 1);
                    int row = q0 + qrow + ((e & 2) ? 8 : 0);
                    if (col > row) v = -1e30f;
                }
                sacc[j][e] = v;
            }

        // ---- online softmax ----
#pragma unroll
        for (int half = 0; half < 2; half++) {
            const int e0 = half * 2;
            float rmax = -1e30f;
#pragma unroll
            for (int j = 0; j < 8; j++)
                rmax = fmaxf(rmax, fmaxf(sacc[j][e0], sacc[j][e0 + 1]));
            rmax = fmaxf(rmax, __shfl_xor_sync(0xffffffffu, rmax, 1));
            rmax = fmaxf(rmax, __shfl_xor_sync(0xffffffffu, rmax, 2));
            float mnew = fmaxf(m_s[half], rmax);
            float corr = __expf(m_s[half] - mnew);
            float rsum = 0.f;
#pragma unroll
            for (int j = 0; j < 8; j++) {
                float p0 = __expf(sacc[j][e0] - mnew);
                float p1 = __expf(sacc[j][e0 + 1] - mnew);
                sacc[j][e0] = p0; sacc[j][e0 + 1] = p1;
                rsum += p0 + p1;
            }
            rsum += __shfl_xor_sync(0xffffffffu, rsum, 1);
            rsum += __shfl_xor_sync(0xffffffffu, rsum, 2);
            l_s[half] = l_s[half] * corr + rsum;
            m_s[half] = mnew;
#pragma unroll
            for (int j = 0; j < 16; j++) {
                O[j][e0]     *= corr;
                O[j][e0 + 1] *= corr;
            }
        }

        // ---- P -> smem (tf32-rounded, per-warp region) ----
#pragma unroll
        for (int j = 0; j < 8; j++) {
            int ck = 2 * j + (c >> 1);
            int off = swz(r, ck) * 4 + (c & 1) * 2;
            *(float2*)&Ps[qrow * 64 + off] =
                make_float2(rnd_tf32(sacc[j][0]), rnd_tf32(sacc[j][1]));
            *(float2*)&Ps[(qrow + 8) * 64 + off] =
                make_float2(rnd_tf32(sacc[j][2]), rnd_tf32(sacc[j][3]));
        }
        __syncwarp();

        // ---- O += P V ----
#pragma unroll
        for (int ks = 0; ks < 8; ks++) {
            const int ea = swz(lane7, 2 * ks + a_sel) << 4;
            const int eb = swz(lane7, 2 * ks + b_sel) << 4;
            uint32_t a[4];
            ldsm4(a, Ps_u + a_roP + ea);
#pragma unroll
            for (int jp = 0; jp < 8; jp++) {
                uint32_t bf[4];
                ldsm4(bf, Vs_u + b_roV[jp] + eb);
                mma_tf32(O[2 * jp],     a, &bf[0]);
                mma_tf32(O[2 * jp + 1], a, &bf[2]);
            }
        }

        // ---- refill single KV buffer ----
        if (kb + 1 < nkb) {
            __syncthreads();
            issueKV(kb + 1);
            asm volatile("cp.async.wait_group 0;\n");
            __syncthreads();
        }
    }

    const int b = bh >> 4, h = bh & 15;
    const float inv0 = 1.f / l_s[0];
    const float inv1 = 1.f / l_s[1];
    const int row0 = q0 + qrow, row1 = row0 + 8;
#pragma unroll
    for (int j = 0; j < 16; j++) {
        int n = h * HDIM + j * 8 + 2 * c;
        *(float2*)&g_attn[(size_t)(b * SEQ + row0) * HID + n] =
            make_float2(rnd_tf32(O[j][0] * inv0), rnd_tf32(O[j][1] * inv0));
        *(float2*)&g_attn[(size_t)(b * SEQ + row1) * HID + n] =
            make_float2(rnd_tf32(O[j][2] * inv1), rnd_tf32(O[j][3] * inv1));
    }
}

// ---------------------------------------------------------------------------
extern "C" void kernel_launch(void* const* d_in, const int* in_sizes, int n_in,
                              void* d_out, int out_size)
{
    const float* x  = (const float*)d_in[0];
    const float* Wq = (const float*)d_in[1];
    const float* bq = (const float*)d_in[2];
    const float* Wk = (const float*)d_in[3];
    const float* bk = (const float*)d_in[4];
    const float* Wv = (const float*)d_in[5];
    const float* bv = (const float*)d_in[6];
    const float* Wo = (const float*)d_in[7];
    const float* bo = (const float*)d_in[8];
    float* out = (float*)d_out;

    float *q, *k, *vt, *attn, *xr, *wr, *bcat;
    cudaGetSymbolAddress((void**)&q,    g_Q);
    cudaGetSymbolAddress((void**)&k,    g_K);
    cudaGetSymbolAddress((void**)&vt,   g_Vt);
    cudaGetSymbolAddress((void**)&attn, g_attn);
    cudaGetSymbolAddress((void**)&xr,   g_xr);
    cudaGetSymbolAddress((void**)&wr,   g_Wr);
    cudaGetSymbolAddress((void**)&bcat, g_bqkv);

    const size_t gemm_smem = BUF_FLOATS * 2 * sizeof(float);        // 64 KB
    cudaFuncSetAttribute(gemm_qkv_kernel,
                         cudaFuncAttributeMaxDynamicSharedMemorySize, (int)gemm_smem);
    cudaFuncSetAttribute(gemm_o_kernel,
                         cudaFuncAttributeMaxDynamicSharedMemorySize, (int)gemm_smem);
    const size_t attn_smem = ATTN_SMEM_FLOATS * sizeof(float);      // 112 KB
    cudaFuncSetAttribute(attn_tc_kernel,
                         cudaFuncAttributeMaxDynamicSharedMemorySize, (int)attn_smem);

    float* wo_r = wr + 3ull * HID * HID;

    // fused prologue: x-round (8192 blocks) + 4 weight-rounds (16384 blocks)
    prep_kernel<<<8192 + 16384, 256>>>(x, Wq, Wk, Wv, Wo, bq, bk, bv,
                                       xr, wr, bcat);

    gemm_qkv_kernel<<<dim3(3 * HID / 128, MROWS / 128), 256, gemm_smem>>>(
        xr, wr, q, k, vt);
    attn_tc_kernel<<<dim3(SEQ / 64, BH), 128, attn_smem>>>();
    gemm_o_kernel<<<dim3(HID / 128, MROWS / 128), 256, gemm_smem>>>(
        attn, wo_r, bo, out);
}

// round 13
// speedup vs baseline: 1.0386x; 1.0119x over previous
#include <cuda_runtime.h>
#include <cstdint>

#define HID   2048
#define MROWS 4096   // B*S
#define NHEAD 16
#define HDIM  128
#define SEQ   2048
#define BH    32     // B*NHEAD

// Scratch (no allocations allowed)
__device__ float g_Q [BH * SEQ * HDIM];       // [bh][s][d]   (tf32-rounded)
__device__ float g_K [BH * SEQ * HDIM];       // [bh][s][d]   (tf32-rounded)
__device__ float g_Vt[BH * HDIM * SEQ];       // [bh][d][s]   (tf32-rounded)
__device__ float g_attn[(size_t)MROWS * HID]; // [B*S][nh*hd] (tf32-rounded)
__device__ float g_xr[(size_t)MROWS * HID];   // rounded x
__device__ float g_Wr[4ull * HID * HID];      // rounded Wq,Wk,Wv,Wo (contiguous)
__device__ float g_bqkv[3 * HID];             // concat bq|bk|bv

// ---------------------------------------------------------------------------
// helpers
// ---------------------------------------------------------------------------
__device__ __forceinline__ void cp_async16(void* smem_dst, const void* gmem_src) {
    uint32_t s = (uint32_t)__cvta_generic_to_shared(smem_dst);
    asm volatile("cp.async.cg.shared.global [%0], [%1], 16;\n" :: "r"(s), "l"(gmem_src));
}
__device__ __forceinline__ float rnd_tf32(float f) {
    uint32_t u;
    asm("cvt.rna.tf32.f32 %0, %1;" : "=r"(u) : "f"(f));
    return __uint_as_float(u);
}
__device__ __forceinline__ void mma_tf32(float* d, const uint32_t* a, const uint32_t* b) {
    asm volatile(
        "mma.sync.aligned.m16n8k8.row.col.f32.tf32.tf32.f32 "
        "{%0,%1,%2,%3}, {%4,%5,%6,%7}, {%8,%9}, {%0,%1,%2,%3};"
        : "+f"(d[0]), "+f"(d[1]), "+f"(d[2]), "+f"(d[3])
        : "r"(a[0]), "r"(a[1]), "r"(a[2]), "r"(a[3]), "r"(b[0]), "r"(b[1]));
}
__device__ __forceinline__ void ldsm4(uint32_t* d, uint32_t addr) {
    asm volatile("ldmatrix.sync.aligned.m8n8.x4.shared.b16 {%0,%1,%2,%3}, [%4];"
        : "=r"(d[0]), "=r"(d[1]), "=r"(d[2]), "=r"(d[3]) : "r"(addr));
}
__device__ __forceinline__ int swz(int row, int ck) {
    return (ck & ~7) | ((ck ^ row) & 7);
}
__device__ __forceinline__ uint32_t smem_u32(const void* p) {
    return (uint32_t)__cvta_generic_to_shared(p);
}

// ---------------------------------------------------------------------------
// Fused prologue: tf32-round x and all 4 weights, concat biases.
// ---------------------------------------------------------------------------
__global__ __launch_bounds__(256)
void prep_kernel(const float* __restrict__ x,
                 const float* __restrict__ w0, const float* __restrict__ w1,
                 const float* __restrict__ w2, const float* __restrict__ w3,
                 const float* __restrict__ bq, const float* __restrict__ bk,
                 const float* __restrict__ bv,
                 float* __restrict__ xr, float* __restrict__ wr,
                 float* __restrict__ bcat)
{
    const int blk = blockIdx.x;
    const int tid = threadIdx.x;

    int bi = blk * 256 + tid;
    if (bi < 3 * HID) {
        const float* s = (bi < HID) ? bq : (bi < 2 * HID) ? bk : bv;
        bcat[bi] = s[bi & (HID - 1)];
    }

    const float4* src;
    float4* dst;
    int idx;
    if (blk < 8192) {
        idx = blk * 256 + tid;
        src = (const float4*)x;
        dst = (float4*)xr;
    } else {
        int wb = blk - 8192;
        int which = wb >> 12;
        idx = (wb & 4095) * 256 + tid;
        src = (const float4*)((which == 0) ? w0 : (which == 1) ? w1 :
                              (which == 2) ? w2 : w3);
        dst = (float4*)(wr + (size_t)which * HID * HID);
    }
    float4 v = src[idx];
    v.x = rnd_tf32(v.x); v.y = rnd_tf32(v.y);
    v.z = rnd_tf32(v.z); v.w = rnd_tf32(v.w);
    dst[idx] = v;
}

// ---------------------------------------------------------------------------
// GEMMs: exact round-7 structure (2-stage, issue-before-wait, two syncs).
// ---------------------------------------------------------------------------
#define BK 32
#define NKT (HID / BK)   // 64
#define BUF_FLOATS 8192

__global__ __launch_bounds__(256, 2)
void gemm_qkv_kernel(const float* __restrict__ A,
                     const float* __restrict__ Wcat,
                     float* __restrict__ qout,
                     float* __restrict__ kout,
                     float* __restrict__ vout)
{
    extern __shared__ float sm[];
    const int t    = threadIdx.x;
    const int lane = t & 31;
    const int wid  = t >> 5;
    const int wm   = wid & 3;
    const int wn   = wid >> 2;
    const int m0   = blockIdx.y * 128;
    const int n0g  = blockIdx.x * 128;
    const int mat  = blockIdx.x >> 4;          // 0=Q 1=K 2=V
    const int r = lane >> 2;
    const int c = lane & 3;

    const int lane7 = lane & 7;
    const int a_sel = (lane >> 4) & 1;
    const int a_i16 = ((lane >> 3) & 1) * 8;
    const int b_sel = (lane >> 3) & 1;
    const int b_n8  = ((lane >> 4) & 1) * 8;

    const int a_ro0 = (wm * 32 + a_i16 + lane7) * 128;
    const int a_ro1 = a_ro0 + 16 * 128;
    int b_ro[4];
#pragma unroll
    for (int jp = 0; jp < 4; jp++)
        b_ro[jp] = (wn * 64 + jp * 16 + b_n8 + lane7) * 128;

    float acc[2][8][4];
#pragma unroll
    for (int i = 0; i < 2; i++)
#pragma unroll
        for (int j = 0; j < 8; j++)
#pragma unroll
            for (int e = 0; e < 4; e++) acc[i][j][e] = 0.f;

    auto issue_tile = [&](int kt, int buf) {
        float* As = sm + buf * BUF_FLOATS;
        float* Ws = As + 4096;
        const int k0 = kt * BK;
#pragma unroll
        for (int i = 0; i < 4; i++) {
            int id  = t + i * 256;
            int row = id >> 3;
            int ck  = id & 7;
            int swk = (ck ^ (row & 7)) << 2;
            cp_async16(As + row * 32 + swk,
                       A + (size_t)(m0 + row) * HID + k0 + ck * 4);
            cp_async16(Ws + row * 32 + swk,
                       Wcat + (size_t)(n0g + row) * HID + k0 + ck * 4);
        }
        asm volatile("cp.async.commit_group;\n");
    };

    issue_tile(0, 0);
    const uint32_t smbase = smem_u32(sm);

    for (int kt = 0; kt < NKT; kt++) {
        if (kt + 1 < NKT) {
            issue_tile(kt + 1, (kt + 1) & 1);
            asm volatile("cp.async.wait_group 1;\n");
        } else {
            asm volatile("cp.async.wait_group 0;\n");
        }
        __syncthreads();

        const uint32_t smA = smbase + (kt & 1) * (BUF_FLOATS * 4);
        const uint32_t smB = smA + 16384;

#pragma unroll
        for (int ks = 0; ks < 4; ks++) {
            const int ea = (((2 * ks + a_sel) ^ lane7) << 4);
            const int eb = (((2 * ks + b_sel) ^ lane7) << 4);
            uint32_t af0[4], af1[4];
            ldsm4(af0, smA + a_ro0 + ea);
            ldsm4(af1, smA + a_ro1 + ea);
#pragma unroll
            for (int jp = 0; jp < 4; jp++) {
                uint32_t bf[4];
                ldsm4(bf, smB + b_ro[jp] + eb);
                mma_tf32(acc[0][2 * jp],     af0, &bf[0]);
                mma_tf32(acc[0][2 * jp + 1], af0, &bf[2]);
                mma_tf32(acc[1][2 * jp],     af1, &bf[0]);
                mma_tf32(acc[1][2 * jp + 1], af1, &bf[2]);
            }
        }
        __syncthreads();
    }

    float* outQK = (mat == 0) ? qout : kout;

#pragma unroll
    for (int i = 0; i < 2; i++) {
        int r0 = m0 + wm * 32 + i * 16 + r;
        int r1 = r0 + 8;
        int b_0 = r0 >> 11, s_0 = r0 & 2047;
        int b_1 = r1 >> 11, s_1 = r1 & 2047;
#pragma unroll
        for (int j = 0; j < 8; j++) {
            int nbg = n0g + wn * 64 + j * 8 + 2 * c;
            int nb  = nbg & 2047;
            float b0 = g_bqkv[nbg], b1 = g_bqkv[nbg + 1];
            float d00 = rnd_tf32(acc[i][j][0] + b0);
            float d01 = rnd_tf32(acc[i][j][1] + b1);
            float d10 = rnd_tf32(acc[i][j][2] + b0);
            float d11 = rnd_tf32(acc[i][j][3] + b1);
            int h = nb >> 7, d = nb & 127;
            if (mat < 2) {
                *(float2*)&outQK[(size_t)((b_0 * NHEAD + h) * SEQ + s_0) * HDIM + d] =
                    make_float2(d00, d01);
                *(float2*)&outQK[(size_t)((b_1 * NHEAD + h) * SEQ + s_1) * HDIM + d] =
                    make_float2(d10, d11);
            } else {
                size_t base0 = (size_t)((b_0 * NHEAD + h) * HDIM + d) * SEQ;
                size_t base1 = (size_t)((b_1 * NHEAD + h) * HDIM + d) * SEQ;
                vout[base0 + s_0]       = d00;
                vout[base0 + SEQ + s_0] = d01;
                vout[base1 + s_1]       = d10;
                vout[base1 + SEQ + s_1] = d11;
            }
        }
    }
}

__global__ __launch_bounds__(256, 2)
void gemm_o_kernel(const float* __restrict__ A,
                   const float* __restrict__ W,
                   const float* __restrict__ bias,
                   float* __restrict__ out)
{
    extern __shared__ float sm[];
    const int t    = threadIdx.x;
    const int lane = t & 31;
    const int wid  = t >> 5;
    const int wm   = wid & 3;
    const int wn   = wid >> 2;
    const int m0   = blockIdx.y * 128;
    const int n0   = blockIdx.x * 128;
    const int r = lane >> 2;
    const int c = lane & 3;

    const int lane7 = lane & 7;
    const int a_sel = (lane >> 4) & 1;
    const int a_i16 = ((lane >> 3) & 1) * 8;
    const int b_sel = (lane >> 3) & 1;
    const int b_n8  = ((lane >> 4) & 1) * 8;

    const int a_ro0 = (wm * 32 + a_i16 + lane7) * 128;
    const int a_ro1 = a_ro0 + 16 * 128;
    int b_ro[4];
#pragma unroll
    for (int jp = 0; jp < 4; jp++)
        b_ro[jp] = (wn * 64 + jp * 16 + b_n8 + lane7) * 128;

    float acc[2][8][4];
#pragma unroll
    for (int i = 0; i < 2; i++)
#pragma unroll
        for (int j = 0; j < 8; j++)
#pragma unroll
            for (int e = 0; e < 4; e++) acc[i][j][e] = 0.f;

    auto issue_tile = [&](int kt, int buf) {
        float* As = sm + buf * BUF_FLOATS;
        float* Ws = As + 4096;
        const int k0 = kt * BK;
#pragma unroll
        for (int i = 0; i < 4; i++) {
            int id  = t + i * 256;
            int row = id >> 3;
            int ck  = id & 7;
            int swk = (ck ^ (row & 7)) << 2;
            cp_async16(As + row * 32 + swk,
                       A + (size_t)(m0 + row) * HID + k0 + ck * 4);
            cp_async16(Ws + row * 32 + swk,
                       W + (size_t)(n0 + row) * HID + k0 + ck * 4);
        }
        asm volatile("cp.async.commit_group;\n");
    };

    issue_tile(0, 0);
    const uint32_t smbase = smem_u32(sm);

    for (int kt = 0; kt < NKT; kt++) {
        if (kt + 1 < NKT) {
            issue_tile(kt + 1, (kt + 1) & 1);
            asm volatile("cp.async.wait_group 1;\n");
        } else {
            asm volatile("cp.async.wait_group 0;\n");
        }
        __syncthreads();

        const uint32_t smA = smbase + (kt & 1) * (BUF_FLOATS * 4);
        const uint32_t smB = smA + 16384;

#pragma unroll
        for (int ks = 0; ks < 4; ks++) {
            const int ea = (((2 * ks + a_sel) ^ lane7) << 4);
            const int eb = (((2 * ks + b_sel) ^ lane7) << 4);
            uint32_t af0[4], af1[4];
            ldsm4(af0, smA + a_ro0 + ea);
            ldsm4(af1, smA + a_ro1 + ea);
#pragma unroll
            for (int jp = 0; jp < 4; jp++) {
                uint32_t bf[4];
                ldsm4(bf, smB + b_ro[jp] + eb);
                mma_tf32(acc[0][2 * jp],     af0, &bf[0]);
                mma_tf32(acc[0][2 * jp + 1], af0, &bf[2]);
                mma_tf32(acc[1][2 * jp],     af1, &bf[0]);
                mma_tf32(acc[1][2 * jp + 1], af1, &bf[2]);
            }
        }
        __syncthreads();
    }

#pragma unroll
    for (int i = 0; i < 2; i++) {
        int r0 = m0 + wm * 32 + i * 16 + r;
        int r1 = r0 + 8;
#pragma unroll
        for (int j = 0; j < 8; j++) {
            int nb = n0 + wn * 64 + j * 8 + 2 * c;
            float b0 = bias[nb], b1 = bias[nb + 1];
            *(float2*)&out[(size_t)r0 * HID + nb] =
                make_float2(acc[i][j][0] + b0, acc[i][j][1] + b1);
            *(float2*)&out[(size_t)r1 * HID + nb] =
                make_float2(acc[i][j][2] + b0, acc[i][j][3] + b1);
        }
    }
}

// ---------------------------------------------------------------------------
// Flash attention — r9 structure + Q fragments cached in registers.
// 128-thread CTAs, q-tile 64, single-buffered KV, 2 CTAs/SM.
// smem: Q 8192 | K 8192 | V 8192 | P 4096 floats = 112 KB
// ---------------------------------------------------------------------------
#define AQ_OFF 0
#define AK_OFF 8192
#define AV_OFF 16384
#define AP_OFF 24576
#define ATTN_SMEM_FLOATS 28672   // 114688 bytes

__global__ __launch_bounds__(128, 2)
void attn_tc_kernel()
{
    extern __shared__ float sm[];
    float* Ps = sm + AP_OFF;

    const int t    = threadIdx.x;
    const int lane = t & 31;
    const int w    = t >> 5;       // 0..3
    const int r    = lane >> 2;
    const int c    = lane & 3;
    const int qbI  = 31 - blockIdx.x;   // heavy tiles first
    const int bh   = blockIdx.y;
    const int q0   = qbI * 64;
    const int nkb  = qbI + 1;
    const float scale = 0.08838834764831845f; // 1/sqrt(128)

    const int lane7 = lane & 7;
    const int a_sel = (lane >> 4) & 1;
    const int a_i16 = ((lane >> 3) & 1) * 8;
    const int b_sel = (lane >> 3) & 1;
    const int b_n8  = ((lane >> 4) & 1) * 8;

    const float* Qg = g_Q  + (size_t)bh * SEQ * HDIM;
    const float* Kg = g_K  + (size_t)bh * SEQ * HDIM;
    const float* Vg = g_Vt + (size_t)bh * HDIM * SEQ;

    const uint32_t smu  = smem_u32(sm);
    const uint32_t Qs_u = smu + AQ_OFF * 4;
    const uint32_t Ks_u = smu + AK_OFF * 4;
    const uint32_t Vs_u = smu + AV_OFF * 4;
    const uint32_t Ps_u = smu + AP_OFF * 4;

    const int a_roQ = (w * 16 + a_i16 + lane7) * 512;
    const int a_roP = (w * 16 + a_i16 + lane7) * 256;
    int b_roK[4];
#pragma unroll
    for (int jp = 0; jp < 4; jp++)
        b_roK[jp] = (jp * 16 + b_n8 + lane7) * 512;
    int b_roV[8];
#pragma unroll
    for (int jp = 0; jp < 8; jp++)
        b_roV[jp] = (jp * 16 + b_n8 + lane7) * 256;

    auto issueKV = [&](int kb) {
        const int k0 = kb * 64;
#pragma unroll
        for (int i = 0; i < 16; i++) {       // K: 64 rows x 32 chunks
            int id = t + i * 128;
            int row = id >> 5, ck = id & 31;
            cp_async16(sm + AK_OFF + row * 128 + swz(row & 7, ck) * 4,
                       Kg + (size_t)(k0 + row) * HDIM + ck * 4);
        }
#pragma unroll
        for (int i = 0; i < 16; i++) {       // V: 128 d-rows x 16 chunks
            int id = t + i * 128;
            int row = id >> 4, ck = id & 15;
            cp_async16(sm + AV_OFF + row * 64 + swz(row & 7, ck) * 4,
                       Vg + (size_t)row * SEQ + k0 + ck * 4);
        }
        asm volatile("cp.async.commit_group;\n");
    };

    // prologue: Q (once) + KV(0)
#pragma unroll
    for (int i = 0; i < 16; i++) {
        int id = t + i * 128;
        int row = id >> 5, ck = id & 31;
        cp_async16(sm + AQ_OFF + row * 128 + swz(row & 7, ck) * 4,
                   Qg + (size_t)(q0 + row) * HDIM + ck * 4);
    }
    issueKV(0);
    asm volatile("cp.async.wait_group 0;\n");
    __syncthreads();

    // ---- cache Q fragments in registers (invariant across kb) ----
    uint32_t qf[16][4];
#pragma unroll
    for (int ks = 0; ks < 16; ks++)
        ldsm4(qf[ks], Qs_u + a_roQ + (swz(lane7, 2 * ks + a_sel) << 4));

    float m_s[2], l_s[2], O[16][4];
#pragma unroll
    for (int e = 0; e < 2; e++) { m_s[e] = -1e30f; l_s[e] = 0.f; }
#pragma unroll
    for (int j = 0; j < 16; j++)
#pragma unroll
        for (int e = 0; e < 4; e++) O[j][e] = 0.f;

    const int qrow = w * 16 + r;

    for (int kb = 0; kb < nkb; kb++) {
        const int k0 = kb * 64;

        // ---- S = Q K^T (Q from registers) ----
        float sacc[8][4];
#pragma unroll
        for (int j = 0; j < 8; j++)
#pragma unroll
            for (int e = 0; e < 4; e++) sacc[j][e] = 0.f;

#pragma unroll
        for (int ks = 0; ks < 16; ks++) {
            const int eb = swz(lane7, 2 * ks + b_sel) << 4;
#pragma unroll
            for (int jp = 0; jp < 4; jp++) {
                uint32_t bf[4];
                ldsm4(bf, Ks_u + b_roK[jp] + eb);
                mma_tf32(sacc[2 * jp],     qf[ks], &bf[0]);
                mma_tf32(sacc[2 * jp + 1], qf[ks], &bf[2]);
            }
        }

        // ---- scale + causal mask ----
        const bool need_mask = (kb == nkb - 1);
#pragma unroll
        for (int j = 0; j < 8; j++)
#pragma unroll
            for (int e = 0; e < 4; e++) {
                float v = sacc[j][e] * scale;
                if (need_mask) {
                    int col = k0 + j * 8 + 2 * c + (e & 1);
                    int row = q0 + qrow + ((e & 2) ? 8 : 0);
                    if (col > row) v = -1e30f;
                }
                sacc[j][e] = v;
            }

        // ---- online softmax ----
#pragma unroll
        for (int half = 0; half < 2; half++) {
            const int e0 = half * 2;
            float rmax = -1e30f;
#pragma unroll
            for (int j = 0; j < 8; j++)
                rmax = fmaxf(rmax, fmaxf(sacc[j][e0], sacc[j][e0 + 1]));
            rmax = fmaxf(rmax, __shfl_xor_sync(0xffffffffu, rmax, 1));
            rmax = fmaxf(rmax, __shfl_xor_sync(0xffffffffu, rmax, 2));
            float mnew = fmaxf(m_s[half], rmax);
            float corr = __expf(m_s[half] - mnew);
            float rsum = 0.f;
#pragma unroll
            for (int j = 0; j < 8; j++) {
                float p0 = __expf(sacc[j][e0] - mnew);
                float p1 = __expf(sacc[j][e0 + 1] - mnew);
                sacc[j][e0] = p0; sacc[j][e0 + 1] = p1;
                rsum += p0 + p1;
            }
            rsum += __shfl_xor_sync(0xffffffffu, rsum, 1);
            rsum += __shfl_xor_sync(0xffffffffu, rsum, 2);
            l_s[half] = l_s[half] * corr + rsum;
            m_s[half] = mnew;
#pragma unroll
            for (int j = 0; j < 16; j++) {
                O[j][e0]     *= corr;
                O[j][e0 + 1] *= corr;
            }
        }

        // ---- P -> smem (tf32-rounded, per-warp region) ----
#pragma unroll
        for (int j = 0; j < 8; j++) {
            int ck = 2 * j + (c >> 1);
            int off = swz(r, ck) * 4 + (c & 1) * 2;
            *(float2*)&Ps[qrow * 64 + off] =
                make_float2(rnd_tf32(sacc[j][0]), rnd_tf32(sacc[j][1]));
            *(float2*)&Ps[(qrow + 8) * 64 + off] =
                make_float2(rnd_tf32(sacc[j][2]), rnd_tf32(sacc[j][3]));
        }
        __syncwarp();

        // ---- O += P V ----
#pragma unroll
        for (int ks = 0; ks < 8; ks++) {
            const int ea = swz(lane7, 2 * ks + a_sel) << 4;
            const int eb = swz(lane7, 2 * ks + b_sel) << 4;
            uint32_t a[4];
            ldsm4(a, Ps_u + a_roP + ea);
#pragma unroll
            for (int jp = 0; jp < 8; jp++) {
                uint32_t bf[4];
                ldsm4(bf, Vs_u + b_roV[jp] + eb);
                mma_tf32(O[2 * jp],     a, &bf[0]);
                mma_tf32(O[2 * jp + 1], a, &bf[2]);
            }
        }

        // ---- refill single KV buffer ----
        if (kb + 1 < nkb) {
            __syncthreads();
            issueKV(kb + 1);
            asm volatile("cp.async.wait_group 0;\n");
            __syncthreads();
        }
    }

    const int b = bh >> 4, h = bh & 15;
    const float inv0 = 1.f / l_s[0];
    const float inv1 = 1.f / l_s[1];
    const int row0 = q0 + qrow, row1 = row0 + 8;
#pragma unroll
    for (int j = 0; j < 16; j++) {
        int n = h * HDIM + j * 8 + 2 * c;
        *(float2*)&g_attn[(size_t)(b * SEQ + row0) * HID + n] =
            make_float2(rnd_tf32(O[j][0] * inv0), rnd_tf32(O[j][1] * inv0));
        *(float2*)&g_attn[(size_t)(b * SEQ + row1) * HID + n] =
            make_float2(rnd_tf32(O[j][2] * inv1), rnd_tf32(O[j][3] * inv1));
    }
}

// ---------------------------------------------------------------------------
extern "C" void kernel_launch(void* const* d_in, const int* in_sizes, int n_in,
                              void* d_out, int out_size)
{
    const float* x  = (const float*)d_in[0];
    const float* Wq = (const float*)d_in[1];
    const float* bq = (const float*)d_in[2];
    const float* Wk = (const float*)d_in[3];
    const float* bk = (const float*)d_in[4];
    const float* Wv = (const float*)d_in[5];
    const float* bv = (const float*)d_in[6];
    const float* Wo = (const float*)d_in[7];
    const float* bo = (const float*)d_in[8];
    float* out = (float*)d_out;

    float *q, *k, *vt, *attn, *xr, *wr, *bcat;
    cudaGetSymbolAddress((void**)&q,    g_Q);
    cudaGetSymbolAddress((void**)&k,    g_K);
    cudaGetSymbolAddress((void**)&vt,   g_Vt);
    cudaGetSymbolAddress((void**)&attn, g_attn);
    cudaGetSymbolAddress((void**)&xr,   g_xr);
    cudaGetSymbolAddress((void**)&wr,   g_Wr);
    cudaGetSymbolAddress((void**)&bcat, g_bqkv);

    const size_t gemm_smem = BUF_FLOATS * 2 * sizeof(float);        // 64 KB
    cudaFuncSetAttribute(gemm_qkv_kernel,
                         cudaFuncAttributeMaxDynamicSharedMemorySize, (int)gemm_smem);
    cudaFuncSetAttribute(gemm_o_kernel,
                         cudaFuncAttributeMaxDynamicSharedMemorySize, (int)gemm_smem);
    const size_t attn_smem = ATTN_SMEM_FLOATS * sizeof(float);      // 112 KB
    cudaFuncSetAttribute(attn_tc_kernel,
                         cudaFuncAttributeMaxDynamicSharedMemorySize, (int)attn_smem);

    float* wo_r = wr + 3ull * HID * HID;

    prep_kernel<<<8192 + 16384, 256>>>(x, Wq, Wk, Wv, Wo, bq, bk, bv,
                                       xr, wr, bcat);

    gemm_qkv_kernel<<<dim3(3 * HID / 128, MROWS / 128), 256, gemm_smem>>>(
        xr, wr, q, k, vt);
    attn_tc_kernel<<<dim3(SEQ / 64, BH), 128, attn_smem>>>();
    gemm_o_kernel<<<dim3(HID / 128, MROWS / 128), 256, gemm_smem>>>(
        attn, wo_r, bo, out);
}